// round 16
// baseline (speedup 1.0000x reference)
#include <cuda_runtime.h>
#include <cuda_fp16.h>
#include <math.h>

// Problem constants (fixed by setup_inputs)
#define HW    65536          // 256*256
#define WIMG  256
#define CC    256
#define BB    2
#define NHH   16
#define DHH   16

#define QSCALE 0.3606737602222409f    // 0.25 * log2(e)
#define LOG2E  1.4426950408889634f

// ---------------- scratch (device globals; no allocs allowed) ----------------
// q/k/vd: WINDOW-major fp16: arr[(b*16+h)*1048576 + w*1024 + d*64 + tok]
static __device__ __align__(16) __half g_q [BB*CC*HW];
static __device__ __align__(16) __half g_k [BB*CC*HW];
static __device__ __align__(16) __half g_vd[BB*CC*HW];   // W_v (x1 - x2)
static __device__ __align__(16) float  g_o [BB*CC*HW];   // attn out, window-major
static __device__ __align__(16) __half g_u [BB*CC*HW];   // pooled+dw, image-major
static __device__ __align__(16) float g_pwf[CC*CC];
static __device__ float g_pwb[CC];
static __device__ __align__(16) float g_biasf[NHH*4*8*128*4]; // bias, C-frag layout
static __device__ __align__(16) float g_sx [BB*CC*1024];      // window sums of x2
static __device__ __align__(16) float g_vs [BB*NHH*1024*16];  // 0.5*sum_k v2

// ---------------- prep: fold BN into pointwise weights ----------------
__global__ void prep_kernel(const float* __restrict__ pw,
                            const float* __restrict__ gamma,
                            const float* __restrict__ beta,
                            const float* __restrict__ mean,
                            const float* __restrict__ var)
{
    __shared__ float red[256];
    int o = blockIdx.x, c = threadIdx.x;
    float inv = gamma[c] * rsqrtf(var[c] + 1e-5f);
    float w = pw[o*CC + c];
    g_pwf[o*CC + c] = w * inv;
    red[c] = w * (beta[c] - mean[c]*inv);
    __syncthreads();
    for (int s = 128; s > 0; s >>= 1) {
        if (c < s) red[c] += red[c+s];
        __syncthreads();
    }
    if (c == 0) g_pwb[o] = red[0];
}

// ---------------- bias prep: rel-pos bias in mma C-fragment layout, x log2e ----
__global__ void bias_prep(const float* __restrict__ rel_bias)
{
    int h = blockIdx.x, mi = blockIdx.y, ni = blockIdx.z;
    int lane = threadIdx.x;
    int g = lane >> 2, t = lane & 3;
    float v[4];
    #pragma unroll
    for (int rr = 0; rr < 2; rr++) {
        int i = mi*16 + g + rr*8;
        #pragma unroll
        for (int cc = 0; cc < 2; cc++) {
            int j = ni*8 + 2*t + cc;
            int idx = ((i>>3) - (j>>3) + 7)*15 + ((i&7) - (j&7) + 7);
            v[rr*2 + cc] = LOG2E * rel_bias[idx*NHH + h];
        }
    }
    *(float4*)&g_biasf[(((h*4 + mi)*8 + ni)*128 + lane*4)] =
        make_float4(v[0], v[1], v[2], v[3]);
}

// ---------------- window sums of x2 ----------------
__global__ void xsum_kernel(const float* __restrict__ x2)
{
    int tid = threadIdx.x;
    int wy = blockIdx.x, c = blockIdx.y, b = blockIdx.z;
    const float* xp = x2 + ((size_t)(b*CC + c))*HW + (size_t)(wy*8)*WIMG + tid;
    float s = 0.f;
    #pragma unroll
    for (int r = 0; r < 8; r++) s += xp[(size_t)r*WIMG];
    s += __shfl_xor_sync(0xffffffffu, s, 1);
    s += __shfl_xor_sync(0xffffffffu, s, 2);
    s += __shfl_xor_sync(0xffffffffu, s, 4);
    if ((tid & 7) == 0)
        g_sx[((size_t)(b*CC + c))*1024 + wy*32 + (tid >> 3)] = s;
}

// ---------------- helpers ----------------
__device__ __forceinline__ unsigned f2tf(float x) {
    unsigned r; asm("cvt.rna.tf32.f32 %0, %1;" : "=r"(r) : "f"(x)); return r;
}
__device__ __forceinline__ float ex2(float x) {
    float r; asm("ex2.approx.ftz.f32 %0, %1;" : "=f"(r) : "f"(x)); return r;
}
__device__ __forceinline__ void mma8(float* c, const unsigned* a, const unsigned* b) {
    asm volatile(
        "mma.sync.aligned.m16n8k8.row.col.f32.tf32.tf32.f32 "
        "{%0,%1,%2,%3},{%4,%5,%6,%7},{%8,%9},{%0,%1,%2,%3};"
        : "+f"(c[0]), "+f"(c[1]), "+f"(c[2]), "+f"(c[3])
        : "r"(a[0]), "r"(a[1]), "r"(a[2]), "r"(a[3]), "r"(b[0]), "r"(b[1]));
}
__device__ __forceinline__ void mma16(float* c, const unsigned* a, const unsigned* b) {
    asm volatile(
        "mma.sync.aligned.m16n8k16.row.col.f32.f16.f16.f32 "
        "{%0,%1,%2,%3},{%4,%5,%6,%7},{%8,%9},{%0,%1,%2,%3};"
        : "+f"(c[0]), "+f"(c[1]), "+f"(c[2]), "+f"(c[3])
        : "r"(a[0]), "r"(a[1]), "r"(a[2]), "r"(a[3]), "r"(b[0]), "r"(b[1]));
}
__device__ __forceinline__ unsigned pack_h2(float lo, float hi) {
    __half2 h = __floats2half2_rn(lo, hi);
    return *reinterpret_cast<unsigned*>(&h);
}
__device__ __forceinline__ unsigned h2bits(__half2 h) {
    return *reinterpret_cast<unsigned*>(&h);
}

// ---------------- core fp16 GEMM tile (B source fp32): 128M x 128N, K=256 ----
// 8 warps (4m x 2n), warp tile 32x64, BK=16, double-buffered.
// xb2 != nullptr: B operand is (xb - xb2); bstr = B row stride.
// mode 1: window-major half store. mode 2: vs scatter store (x0.5), hofs = h base.
#define SA2 136

__device__ __forceinline__ void gemm_f16_src32(
    const float* __restrict__ wb,
    const float* __restrict__ xb,
    const float* __restrict__ xb2,
    size_t bstr, int n0,
    __half* __restrict__ obh,
    float* __restrict__ obf,
    int mode, int hofs)
{
    __shared__ __align__(16) unsigned As[2][8*SA2];
    __shared__ __align__(16) unsigned Bs[2][8*SA2];

    int tid  = threadIdx.x;
    int lane = tid & 31, warp = tid >> 5;
    int wm = warp >> 1, wn = warp & 1;
    int gid = lane >> 2, tig = lane & 3;

    float acc[2][8][4];
    #pragma unroll
    for (int mt = 0; mt < 2; mt++)
        #pragma unroll
        for (int nt = 0; nt < 8; nt++)
            #pragma unroll
            for (int i = 0; i < 4; i++) acc[mt][nt][i] = 0.f;

    int arow = tid & 127, akp = (tid >> 7) * 4;
    int bkp  = tid >> 5,  bn4 = (tid & 31) * 4;

    {
        float4 a0 = *(const float4*)(wb + (size_t)arow*CC + akp*2);
        float4 a1 = *(const float4*)(wb + (size_t)arow*CC + akp*2 + 4);
        float4 b0 = *(const float4*)(xb + (size_t)(2*bkp  )*bstr + n0 + bn4);
        float4 b1 = *(const float4*)(xb + (size_t)(2*bkp+1)*bstr + n0 + bn4);
        if (xb2) {
            float4 c0 = *(const float4*)(xb2 + (size_t)(2*bkp  )*bstr + n0 + bn4);
            float4 c1 = *(const float4*)(xb2 + (size_t)(2*bkp+1)*bstr + n0 + bn4);
            b0.x -= c0.x; b0.y -= c0.y; b0.z -= c0.z; b0.w -= c0.w;
            b1.x -= c1.x; b1.y -= c1.y; b1.z -= c1.z; b1.w -= c1.w;
        }
        As[0][(akp+0)*SA2 + arow] = pack_h2(a0.x, a0.y);
        As[0][(akp+1)*SA2 + arow] = pack_h2(a0.z, a0.w);
        As[0][(akp+2)*SA2 + arow] = pack_h2(a1.x, a1.y);
        As[0][(akp+3)*SA2 + arow] = pack_h2(a1.z, a1.w);
        *(uint4*)&Bs[0][bkp*SA2 + bn4] =
            make_uint4(pack_h2(b0.x, b1.x), pack_h2(b0.y, b1.y),
                       pack_h2(b0.z, b1.z), pack_h2(b0.w, b1.w));
    }
    __syncthreads();

    #pragma unroll 2
    for (int it = 0; it < 16; it++) {
        int p = it & 1;
        float4 a0, a1, b0, b1;
        if (it < 15) {
            int k0 = (it + 1) * 16;
            a0 = *(const float4*)(wb + (size_t)arow*CC + k0 + akp*2);
            a1 = *(const float4*)(wb + (size_t)arow*CC + k0 + akp*2 + 4);
            b0 = *(const float4*)(xb + (size_t)(k0 + 2*bkp  )*bstr + n0 + bn4);
            b1 = *(const float4*)(xb + (size_t)(k0 + 2*bkp+1)*bstr + n0 + bn4);
            if (xb2) {
                float4 c0 = *(const float4*)(xb2 + (size_t)(k0 + 2*bkp  )*bstr + n0 + bn4);
                float4 c1 = *(const float4*)(xb2 + (size_t)(k0 + 2*bkp+1)*bstr + n0 + bn4);
                b0.x -= c0.x; b0.y -= c0.y; b0.z -= c0.z; b0.w -= c0.w;
                b1.x -= c1.x; b1.y -= c1.y; b1.z -= c1.z; b1.w -= c1.w;
            }
        }

        unsigned af[2][4], bf[8][2];
        #pragma unroll
        for (int mt = 0; mt < 2; mt++) {
            int m = wm*32 + mt*16 + gid;
            af[mt][0] = As[p][(tig  )*SA2 + m];
            af[mt][1] = As[p][(tig  )*SA2 + m + 8];
            af[mt][2] = As[p][(tig+4)*SA2 + m];
            af[mt][3] = As[p][(tig+4)*SA2 + m + 8];
        }
        #pragma unroll
        for (int nt = 0; nt < 8; nt++) {
            int n = wn*64 + nt*8 + gid;
            bf[nt][0] = Bs[p][(tig  )*SA2 + n];
            bf[nt][1] = Bs[p][(tig+4)*SA2 + n];
        }
        #pragma unroll
        for (int mt = 0; mt < 2; mt++)
            #pragma unroll
            for (int nt = 0; nt < 8; nt++)
                mma16(acc[mt][nt], af[mt], bf[nt]);

        if (it < 15) {
            int q = p ^ 1;
            As[q][(akp+0)*SA2 + arow] = pack_h2(a0.x, a0.y);
            As[q][(akp+1)*SA2 + arow] = pack_h2(a0.z, a0.w);
            As[q][(akp+2)*SA2 + arow] = pack_h2(a1.x, a1.y);
            As[q][(akp+3)*SA2 + arow] = pack_h2(a1.z, a1.w);
            *(uint4*)&Bs[q][bkp*SA2 + bn4] =
                make_uint4(pack_h2(b0.x, b1.x), pack_h2(b0.y, b1.y),
                           pack_h2(b0.z, b1.z), pack_h2(b0.w, b1.w));
        }
        __syncthreads();
    }

    if (mode == 1) {
        // window-major fp16 store: one image row y per block
        int y = n0 >> 8, xb0 = n0 & 255;
        int wy = y >> 3, ty = y & 7;
        #pragma unroll
        for (int mt = 0; mt < 2; mt++) {
            int hloc = wm*2 + mt;
            #pragma unroll
            for (int nt = 0; nt < 8; nt++) {
                int x = xb0 + wn*64 + nt*8 + 2*tig;
                size_t a0 = ((size_t)hloc*1024 + wy*32 + (x>>3))*16;
                int tx = ty*8 + (x&7);
                *reinterpret_cast<__half2*>(obh + (a0 + gid    )*64 + tx) =
                    __floats2half2_rn(acc[mt][nt][0], acc[mt][nt][1]);
                *reinterpret_cast<__half2*>(obh + (a0 + gid + 8)*64 + tx) =
                    __floats2half2_rn(acc[mt][nt][2], acc[mt][nt][3]);
            }
        }
    } else {
        // vs scatter store: rows -> (h, d), cols -> windows; x0.5
        #pragma unroll
        for (int mt = 0; mt < 2; mt++) {
            int r0 = wm*32 + mt*16 + gid;
            int hh = hofs + (r0 >> 4);
            int d0 = r0 & 15, d1 = d0 + 8;
            #pragma unroll
            for (int nt = 0; nt < 8; nt++) {
                int w = n0 + wn*64 + nt*8 + 2*tig;
                obf[((size_t)hh*1024 + w    )*16 + d0] = 0.5f*acc[mt][nt][0];
                obf[((size_t)hh*1024 + w + 1)*16 + d0] = 0.5f*acc[mt][nt][1];
                obf[((size_t)hh*1024 + w    )*16 + d1] = 0.5f*acc[mt][nt][2];
                obf[((size_t)hh*1024 + w + 1)*16 + d1] = 0.5f*acc[mt][nt][3];
            }
        }
    }
}

// ---------------- core fp16 GEMM tile (B source fp16): image store + bias ----
__device__ __forceinline__ void gemm_f16_srch(
    const float* __restrict__ wb,
    const __half* __restrict__ xb,
    float* __restrict__ ob,
    int n0,
    const float* __restrict__ bias)
{
    __shared__ __align__(16) unsigned As[2][8*SA2];
    __shared__ __align__(16) unsigned Bs[2][8*SA2];

    int tid  = threadIdx.x;
    int lane = tid & 31, warp = tid >> 5;
    int wm = warp >> 1, wn = warp & 1;
    int gid = lane >> 2, tig = lane & 3;

    float acc[2][8][4];
    #pragma unroll
    for (int mt = 0; mt < 2; mt++)
        #pragma unroll
        for (int nt = 0; nt < 8; nt++)
            #pragma unroll
            for (int i = 0; i < 4; i++) acc[mt][nt][i] = 0.f;

    int arow = tid & 127, akp = (tid >> 7) * 4;
    int bkp  = tid >> 5,  bn4 = (tid & 31) * 4;

    {
        float4 a0 = *(const float4*)(wb + (size_t)arow*CC + akp*2);
        float4 a1 = *(const float4*)(wb + (size_t)arow*CC + akp*2 + 4);
        uint2 r0 = *(const uint2*)(xb + (size_t)(2*bkp  )*HW + n0 + bn4);
        uint2 r1 = *(const uint2*)(xb + (size_t)(2*bkp+1)*HW + n0 + bn4);
        As[0][(akp+0)*SA2 + arow] = pack_h2(a0.x, a0.y);
        As[0][(akp+1)*SA2 + arow] = pack_h2(a0.z, a0.w);
        As[0][(akp+2)*SA2 + arow] = pack_h2(a1.x, a1.y);
        As[0][(akp+3)*SA2 + arow] = pack_h2(a1.z, a1.w);
        __half2 p0 = *reinterpret_cast<__half2*>(&r0.x);
        __half2 p1 = *reinterpret_cast<__half2*>(&r1.x);
        __half2 q0 = *reinterpret_cast<__half2*>(&r0.y);
        __half2 q1 = *reinterpret_cast<__half2*>(&r1.y);
        *(uint4*)&Bs[0][bkp*SA2 + bn4] =
            make_uint4(h2bits(__lows2half2(p0, p1)), h2bits(__highs2half2(p0, p1)),
                       h2bits(__lows2half2(q0, q1)), h2bits(__highs2half2(q0, q1)));
    }
    __syncthreads();

    #pragma unroll 2
    for (int it = 0; it < 16; it++) {
        int p = it & 1;
        float4 a0, a1;
        uint2 r0, r1;
        if (it < 15) {
            int k0 = (it + 1) * 16;
            a0 = *(const float4*)(wb + (size_t)arow*CC + k0 + akp*2);
            a1 = *(const float4*)(wb + (size_t)arow*CC + k0 + akp*2 + 4);
            r0 = *(const uint2*)(xb + (size_t)(k0 + 2*bkp  )*HW + n0 + bn4);
            r1 = *(const uint2*)(xb + (size_t)(k0 + 2*bkp+1)*HW + n0 + bn4);
        }

        unsigned af[2][4], bf[8][2];
        #pragma unroll
        for (int mt = 0; mt < 2; mt++) {
            int m = wm*32 + mt*16 + gid;
            af[mt][0] = As[p][(tig  )*SA2 + m];
            af[mt][1] = As[p][(tig  )*SA2 + m + 8];
            af[mt][2] = As[p][(tig+4)*SA2 + m];
            af[mt][3] = As[p][(tig+4)*SA2 + m + 8];
        }
        #pragma unroll
        for (int nt = 0; nt < 8; nt++) {
            int n = wn*64 + nt*8 + gid;
            bf[nt][0] = Bs[p][(tig  )*SA2 + n];
            bf[nt][1] = Bs[p][(tig+4)*SA2 + n];
        }
        #pragma unroll
        for (int mt = 0; mt < 2; mt++)
            #pragma unroll
            for (int nt = 0; nt < 8; nt++)
                mma16(acc[mt][nt], af[mt], bf[nt]);

        if (it < 15) {
            int q = p ^ 1;
            As[q][(akp+0)*SA2 + arow] = pack_h2(a0.x, a0.y);
            As[q][(akp+1)*SA2 + arow] = pack_h2(a0.z, a0.w);
            As[q][(akp+2)*SA2 + arow] = pack_h2(a1.x, a1.y);
            As[q][(akp+3)*SA2 + arow] = pack_h2(a1.z, a1.w);
            __half2 p0 = *reinterpret_cast<__half2*>(&r0.x);
            __half2 p1 = *reinterpret_cast<__half2*>(&r1.x);
            __half2 q0 = *reinterpret_cast<__half2*>(&r0.y);
            __half2 q1 = *reinterpret_cast<__half2*>(&r1.y);
            *(uint4*)&Bs[q][bkp*SA2 + bn4] =
                make_uint4(h2bits(__lows2half2(p0, p1)), h2bits(__highs2half2(p0, p1)),
                           h2bits(__lows2half2(q0, q1)), h2bits(__highs2half2(q0, q1)));
        }
        __syncthreads();
    }

    #pragma unroll
    for (int mt = 0; mt < 2; mt++) {
        int r0 = wm*32 + mt*16 + gid;
        float bia0 = bias[r0], bia1 = bias[r0 + 8];
        #pragma unroll
        for (int nt = 0; nt < 8; nt++) {
            int c = n0 + wn*64 + nt*8 + 2*tig;
            *(float2*)(ob + (size_t)r0*HW + c) =
                make_float2(acc[mt][nt][0] + bia0, acc[mt][nt][1] + bia0);
            *(float2*)(ob + (size_t)(r0+8)*HW + c) =
                make_float2(acc[mt][nt][2] + bia1, acc[mt][nt][3] + bia1);
        }
    }
}

// ---------------- qkv GEMM: q from x1, k from x2, vd from (x1-x2) ------------
__global__ void __launch_bounds__(256, 2) qkv_gemm(const float* __restrict__ x1,
                                                   const float* __restrict__ x2,
                                                   const float* __restrict__ Wq)
{
    int b  = blockIdx.z;
    int by = blockIdx.y;
    int n0 = blockIdx.x * 128;
    const float* wb;
    const float* xa;
    const float* xd2 = nullptr;
    __half* ob;
    if (by < 2) {
        wb = Wq + (size_t)(by*128)*CC;
        ob = g_q + ((size_t)(b*16 + by*8) << 20);
        xa = x1;
    } else if (by < 4) {
        wb = Wq + (size_t)(256 + (by-2)*128)*CC;
        ob = g_k + ((size_t)(b*16 + (by-2)*8) << 20);
        xa = x2;
    } else {
        wb = Wq + (size_t)(512 + (by-4)*128)*CC;
        ob = g_vd + ((size_t)(b*16 + (by-4)*8) << 20);
        xa = x1; xd2 = x2 + (size_t)b*CC*HW;
    }
    xa += (size_t)b*CC*HW;
    gemm_f16_src32(wb, xa, xd2, HW, n0, ob, nullptr, 1, 0);
}

// ---------------- vs GEMM: g_vs = 0.5 * Wv @ g_sx (tensor cores) -------------
__global__ void __launch_bounds__(256, 2) vsg_gemm(const float* __restrict__ Wq)
{
    int b  = blockIdx.z;
    int by = blockIdx.y;                      // 0..1 (weight row tiles)
    int n0 = blockIdx.x * 128;                // windows
    const float* wb = Wq + (size_t)(512 + by*128)*CC;
    const float* xb = g_sx + (size_t)b*CC*1024;
    float* obf = g_vs + (size_t)b*NHH*1024*16;
    gemm_f16_src32(wb, xb, nullptr, 1024, n0, nullptr, obf, 2, by*8);
}

// ---------------- pointwise GEMM (BN folded, fp16 src, image layout) ---------
__global__ void __launch_bounds__(256, 2) pw_gemm(float* __restrict__ out)
{
    int b  = blockIdx.z;
    int by = blockIdx.y;
    int n0 = blockIdx.x * 128;
    const float* wb = g_pwf + (size_t)(by*128)*CC;
    const __half* xb = g_u + (size_t)b*CC*HW;
    float* ob = out + (size_t)b*CC*HW + (size_t)(by*128)*HW;
    gemm_f16_srch(wb, xb, ob, n0, g_pwb + by*128);
}

// ---------------- window attention: tensor-core (mma tf32, fp16 inputs) ------
// o = softmax(q k^T*0.25 + bias) @ (0.5*vd) + 0.5*sum_k v2
#define TS 72

__global__ void __launch_bounds__(128, 5) attn_kernel()
{
    int wid = blockIdx.x;                 // 0..2047
    int h   = blockIdx.y;                 // 0..15
    int b   = wid >> 10;
    int w   = wid & 1023;
    int tid = threadIdx.x;
    int lane = tid & 31;
    int mt   = tid >> 5;                  // m-tile 0..3 (16 queries each)
    int g = lane >> 2, t = lane & 3;

    __shared__ unsigned sq [16*TS];       // tf32(q * 0.25*log2e)
    __shared__ unsigned sk [16*TS];       // tf32(k)
    __shared__ unsigned svd[16*TS];       // tf32(0.5*vd)
    __shared__ float svs[16];             // 0.5*sum_k v2

    size_t wbase = ((size_t)((b*NHH + h)*1024 + w)) * 1024;

    if (tid < 16) svs[tid] = g_vs[((size_t)((b*NHH + h)*1024 + w))*16 + tid];

    // coalesced load: thread covers 8 consecutive tokens of one d (fp16 in)
    {
        int j = tid & 7, dd = tid >> 3;
        int t0 = j*8;
        size_t off = wbase + dd*64 + t0;
        uint4 qr = *(const uint4*)(g_q + off);
        uint4 kr = *(const uint4*)(g_k + off);
        uint4 vr = *(const uint4*)(g_vd + off);
        const __half2* qh = reinterpret_cast<const __half2*>(&qr);
        const __half2* kh = reinterpret_cast<const __half2*>(&kr);
        const __half2* vh = reinterpret_cast<const __half2*>(&vr);
        unsigned* spq = &sq[dd*TS + t0];
        unsigned* spk = &sk[dd*TS + t0];
        unsigned* spv = &svd[dd*TS + t0];
        #pragma unroll
        for (int i = 0; i < 4; i++) {
            float2 qf = __half22float2(qh[i]);
            float2 kf = __half22float2(kh[i]);
            float2 vf = __half22float2(vh[i]);
            spq[2*i  ] = f2tf(qf.x * QSCALE);
            spq[2*i+1] = f2tf(qf.y * QSCALE);
            spk[2*i  ] = f2tf(kf.x);
            spk[2*i+1] = f2tf(kf.y);
            spv[2*i  ] = f2tf(0.5f * vf.x);
            spv[2*i+1] = f2tf(0.5f * vf.y);
        }
    }
    __syncthreads();

    int r0q = mt*16 + g;
    unsigned aq[2][4];
    #pragma unroll
    for (int kc = 0; kc < 2; kc++) {
        aq[kc][0] = sq[(kc*8+t  )*TS + r0q];
        aq[kc][1] = sq[(kc*8+t  )*TS + r0q + 8];
        aq[kc][2] = sq[(kc*8+t+4)*TS + r0q];
        aq[kc][3] = sq[(kc*8+t+4)*TS + r0q + 8];
    }

    float acc[8][4];
    #pragma unroll
    for (int ni = 0; ni < 8; ni++) {
        float4 bv = *(const float4*)&g_biasf[(((h*4 + mt)*8 + ni)*128 + lane*4)];
        acc[ni][0] = bv.x; acc[ni][1] = bv.y;
        acc[ni][2] = bv.z; acc[ni][3] = bv.w;
    }

    #pragma unroll
    for (int ni = 0; ni < 8; ni++) {
        unsigned bk[2][2];
        #pragma unroll
        for (int kc = 0; kc < 2; kc++) {
            bk[kc][0] = sk[(kc*8+t  )*TS + ni*8 + g];
            bk[kc][1] = sk[(kc*8+t+4)*TS + ni*8 + g];
        }
        mma8(acc[ni], aq[0], bk[0]);
        mma8(acc[ni], aq[1], bk[1]);
    }

    {
        float m0 = -1e30f, m1 = -1e30f;
        #pragma unroll
        for (int ni = 0; ni < 8; ni++) {
            m0 = fmaxf(m0, fmaxf(acc[ni][0], acc[ni][1]));
            m1 = fmaxf(m1, fmaxf(acc[ni][2], acc[ni][3]));
        }
        m0 = fmaxf(m0, __shfl_xor_sync(0xffffffffu, m0, 1));
        m0 = fmaxf(m0, __shfl_xor_sync(0xffffffffu, m0, 2));
        m1 = fmaxf(m1, __shfl_xor_sync(0xffffffffu, m1, 1));
        m1 = fmaxf(m1, __shfl_xor_sync(0xffffffffu, m1, 2));
        float s0 = 0.f, s1 = 0.f;
        #pragma unroll
        for (int ni = 0; ni < 8; ni++) {
            float p0 = ex2(acc[ni][0] - m0);
            float p1 = ex2(acc[ni][1] - m0);
            float p2 = ex2(acc[ni][2] - m1);
            float p3 = ex2(acc[ni][3] - m1);
            acc[ni][0] = p0; acc[ni][1] = p1;
            acc[ni][2] = p2; acc[ni][3] = p3;
            s0 += p0 + p1; s1 += p2 + p3;
        }
        s0 += __shfl_xor_sync(0xffffffffu, s0, 1);
        s0 += __shfl_xor_sync(0xffffffffu, s0, 2);
        s1 += __shfl_xor_sync(0xffffffffu, s1, 1);
        s1 += __shfl_xor_sync(0xffffffffu, s1, 2);
        float i0 = 1.0f / s0, i1 = 1.0f / s1;
        #pragma unroll
        for (int ni = 0; ni < 8; ni++) {
            acc[ni][0] = __uint_as_float(f2tf(acc[ni][0]*i0));
            acc[ni][1] = __uint_as_float(f2tf(acc[ni][1]*i0));
            acc[ni][2] = __uint_as_float(f2tf(acc[ni][2]*i1));
            acc[ni][3] = __uint_as_float(f2tf(acc[ni][3]*i1));
        }
    }

    float av[2][4];
    #pragma unroll
    for (int no = 0; no < 2; no++) {
        float c0 = svs[no*8 + 2*t];
        float c1 = svs[no*8 + 2*t + 1];
        av[no][0] = c0; av[no][1] = c1;
        av[no][2] = c0; av[no][3] = c1;
    }

    int src0 = (g << 2) | (t >> 1);
    int src1 = src0 + 2;
    bool odd = (t & 1);
    #pragma unroll
    for (int kc2 = 0; kc2 < 8; kc2++) {
        float r0 = acc[kc2][0], r1 = acc[kc2][1];
        float r2 = acc[kc2][2], r3 = acc[kc2][3];
        float x00 = __shfl_sync(0xffffffffu, r0, src0);
        float x01 = __shfl_sync(0xffffffffu, r1, src0);
        float x02 = __shfl_sync(0xffffffffu, r2, src0);
        float x03 = __shfl_sync(0xffffffffu, r3, src0);
        float x10 = __shfl_sync(0xffffffffu, r0, src1);
        float x11 = __shfl_sync(0xffffffffu, r1, src1);
        float x12 = __shfl_sync(0xffffffffu, r2, src1);
        float x13 = __shfl_sync(0xffffffffu, r3, src1);
        unsigned pa[4];
        pa[0] = __float_as_uint(odd ? x01 : x00);
        pa[1] = __float_as_uint(odd ? x03 : x02);
        pa[2] = __float_as_uint(odd ? x11 : x10);
        pa[3] = __float_as_uint(odd ? x13 : x12);
        unsigned bv[2][2];
        #pragma unroll
        for (int no = 0; no < 2; no++) {
            bv[no][0] = svd[(no*8+g)*TS + kc2*8 + t];
            bv[no][1] = svd[(no*8+g)*TS + kc2*8 + t + 4];
        }
        mma8(av[0], pa, bv[0]);
        mma8(av[1], pa, bv[1]);
    }

    float* op = g_o + wbase;
    int q0 = mt*16 + g;
    #pragma unroll
    for (int no = 0; no < 2; no++) {
        int d0 = no*8 + 2*t;
        op[(d0  )*64 + q0    ] = av[no][0];
        op[(d0+1)*64 + q0    ] = av[no][1];
        op[(d0  )*64 + q0 + 8] = av[no][2];
        op[(d0+1)*64 + q0 + 8] = av[no][3];
    }
}

// ---------------- FUSED pools + pad_out + depthwise (fp16 u out) -------------
__global__ void __launch_bounds__(256) pooldw_kernel(const float* __restrict__ dw)
{
    __shared__ float so[47][48];
    __shared__ float st[39][41];
    __shared__ float sdw[64];
    int bc = blockIdx.z;                       // b*256 + c
    int b = bc >> 8, c = bc & 255;
    int y0 = blockIdx.y*32, x0 = blockIdx.x*32;
    const float* ob = g_o + ((size_t)(b*16 + (c>>4)) << 20) + (size_t)(c & 15)*64;
    int tid = threadIdx.x;
    if (tid < 64) sdw[tid] = dw[c*64 + tid];

    for (int idx = tid; idx < 47*47; idx += 256) {
        int r = idx / 47, cl = idx - r*47;
        int gy = y0 - 6 + r, gx = x0 - 6 + cl;
        float v = 0.f;
        if (gy >= 0 && gy <= 256 && gx >= 0 && gx <= 256) {
            int yy = (gy == 256) ? 254 : gy;
            int xx = (gx == 256) ? 254 : gx;
            v = ob[((size_t)((yy>>3)*32 + (xx>>3)))*1024 + (yy&7)*8 + (xx&7)];
        }
        so[r][cl] = v;
    }
    __syncthreads();

    for (int idx = tid; idx < 39*39; idx += 256) {
        int r = idx / 39, cl = idx - r*39;
        int ty = y0 - 3 + r, tx = x0 - 3 + cl;
        float v = 0.f;
        if (ty >= 0 && ty < 256 && tx >= 0 && tx < 256) {
            float sx = 0.f, sy = 0.f;
            #pragma unroll
            for (int d2 = 0; d2 < 8; d2++) {
                sx += so[r + d2][cl + 3];
                sy += so[r + 3][cl + d2];
            }
            v = (sx + sy)*0.125f;
        }
        st[r][cl] = v;
    }
    __syncthreads();

    int oy = tid >> 3, ox = (tid & 7)*4;
    float a0 = 0.f, a1 = 0.f, a2 = 0.f, a3 = 0.f;
    #pragma unroll
    for (int ky = 0; ky < 8; ky++) {
        const float* row = &st[oy+ky][ox];
        #pragma unroll
        for (int kx = 0; kx < 8; kx++) {
            float wv = sdw[ky*8 + kx];
            a0 += wv*row[kx];
            a1 += wv*row[kx+1];
            a2 += wv*row[kx+2];
            a3 += wv*row[kx+3];
        }
    }
    __half* up = g_u + (size_t)bc*HW + (size_t)(y0+oy)*WIMG + x0 + ox;
    __half2 h0 = __floats2half2_rn(a0, a1);
    __half2 h1 = __floats2half2_rn(a2, a3);
    uint2 pkt = make_uint2(h2bits(h0), h2bits(h1));
    *(uint2*)up = pkt;
}

// ---------------- launch ----------------
extern "C" void kernel_launch(void* const* d_in, const int* in_sizes, int n_in,
                              void* d_out, int out_size)
{
    const float* x1       = (const float*)d_in[0];
    const float* x2       = (const float*)d_in[1];
    const float* qkv_w    = (const float*)d_in[2];
    const float* rel_bias = (const float*)d_in[3];
    const float* dw_w     = (const float*)d_in[4];
    const float* bn_g     = (const float*)d_in[5];
    const float* bn_b     = (const float*)d_in[6];
    const float* bn_m     = (const float*)d_in[7];
    const float* bn_v     = (const float*)d_in[8];
    const float* pw_w     = (const float*)d_in[9];
    float* out = (float*)d_out;

    prep_kernel<<<256, 256>>>(pw_w, bn_g, bn_b, bn_m, bn_v);
    bias_prep<<<dim3(NHH, 4, 8), 32>>>(rel_bias);
    xsum_kernel<<<dim3(32, CC, BB), 256>>>(x2);
    vsg_gemm<<<dim3(8, 2, BB), 256>>>(qkv_w);
    qkv_gemm<<<dim3(512, 6, BB), 256>>>(x1, x2, qkv_w);
    attn_kernel<<<dim3(2048, NHH), 128>>>();
    pooldw_kernel<<<dim3(8, 8, BB*CC), 256>>>(dw_w);
    pw_gemm<<<dim3(512, 2, BB), 256>>>(out);
}

// round 17
// speedup vs baseline: 1.5210x; 1.5210x over previous
#include <cuda_runtime.h>
#include <cuda_fp16.h>
#include <math.h>

// Problem constants (fixed by setup_inputs)
#define HW    65536          // 256*256
#define WIMG  256
#define CC    256
#define BB    2
#define NHH   16
#define DHH   16

#define QSCALE 0.3606737602222409f    // 0.25 * log2(e)
#define LOG2E  1.4426950408889634f

// ---------------- scratch (device globals; no allocs allowed) ----------------
// q/k/vd: WINDOW-major fp16: arr[(b*16+h)*1048576 + w*1024 + d*64 + tok]
static __device__ __align__(16) __half g_q [BB*CC*HW];
static __device__ __align__(16) __half g_k [BB*CC*HW];
static __device__ __align__(16) __half g_vd[BB*CC*HW];   // W_v (x1 - x2)
static __device__ __align__(16) float  g_o [BB*CC*HW];   // attn out, window-major
static __device__ __align__(16) __half g_u [BB*CC*HW];   // pooled+dw, image-major
static __device__ __align__(16) float g_pwf[CC*CC];
static __device__ float g_pwb[CC];
static __device__ __align__(16) float g_biasf[NHH*4*8*128*4]; // bias, C-frag layout
static __device__ __align__(16) float g_sx [BB*CC*1024];      // window sums of x2
static __device__ __align__(16) float g_vs [BB*NHH*1024*16];  // 0.5*sum_k v2

// ---------------- prep: fold BN into pointwise weights ----------------
__global__ void prep_kernel(const float* __restrict__ pw,
                            const float* __restrict__ gamma,
                            const float* __restrict__ beta,
                            const float* __restrict__ mean,
                            const float* __restrict__ var)
{
    __shared__ float red[256];
    int o = blockIdx.x, c = threadIdx.x;
    float inv = gamma[c] * rsqrtf(var[c] + 1e-5f);
    float w = pw[o*CC + c];
    g_pwf[o*CC + c] = w * inv;
    red[c] = w * (beta[c] - mean[c]*inv);
    __syncthreads();
    for (int s = 128; s > 0; s >>= 1) {
        if (c < s) red[c] += red[c+s];
        __syncthreads();
    }
    if (c == 0) g_pwb[o] = red[0];
}

// ---------------- bias prep: rel-pos bias in mma C-fragment layout, x log2e ----
__global__ void bias_prep(const float* __restrict__ rel_bias)
{
    int h = blockIdx.x, mi = blockIdx.y, ni = blockIdx.z;
    int lane = threadIdx.x;
    int g = lane >> 2, t = lane & 3;
    float v[4];
    #pragma unroll
    for (int rr = 0; rr < 2; rr++) {
        int i = mi*16 + g + rr*8;
        #pragma unroll
        for (int cc = 0; cc < 2; cc++) {
            int j = ni*8 + 2*t + cc;
            int idx = ((i>>3) - (j>>3) + 7)*15 + ((i&7) - (j&7) + 7);
            v[rr*2 + cc] = LOG2E * rel_bias[idx*NHH + h];
        }
    }
    *(float4*)&g_biasf[(((h*4 + mi)*8 + ni)*128 + lane*4)] =
        make_float4(v[0], v[1], v[2], v[3]);
}

// ---------------- window sums of x2 ----------------
__global__ void xsum_kernel(const float* __restrict__ x2)
{
    int tid = threadIdx.x;
    int wy = blockIdx.x, c = blockIdx.y, b = blockIdx.z;
    const float* xp = x2 + ((size_t)(b*CC + c))*HW + (size_t)(wy*8)*WIMG + tid;
    float s = 0.f;
    #pragma unroll
    for (int r = 0; r < 8; r++) s += xp[(size_t)r*WIMG];
    s += __shfl_xor_sync(0xffffffffu, s, 1);
    s += __shfl_xor_sync(0xffffffffu, s, 2);
    s += __shfl_xor_sync(0xffffffffu, s, 4);
    if ((tid & 7) == 0)
        g_sx[((size_t)(b*CC + c))*1024 + wy*32 + (tid >> 3)] = s;
}

// ---------------- helpers ----------------
__device__ __forceinline__ unsigned f2tf(float x) {
    unsigned r; asm("cvt.rna.tf32.f32 %0, %1;" : "=r"(r) : "f"(x)); return r;
}
__device__ __forceinline__ float ex2(float x) {
    float r; asm("ex2.approx.ftz.f32 %0, %1;" : "=f"(r) : "f"(x)); return r;
}
__device__ __forceinline__ void mma8(float* c, const unsigned* a, const unsigned* b) {
    asm volatile(
        "mma.sync.aligned.m16n8k8.row.col.f32.tf32.tf32.f32 "
        "{%0,%1,%2,%3},{%4,%5,%6,%7},{%8,%9},{%0,%1,%2,%3};"
        : "+f"(c[0]), "+f"(c[1]), "+f"(c[2]), "+f"(c[3])
        : "r"(a[0]), "r"(a[1]), "r"(a[2]), "r"(a[3]), "r"(b[0]), "r"(b[1]));
}
__device__ __forceinline__ void mma16(float* c, const unsigned* a, const unsigned* b) {
    asm volatile(
        "mma.sync.aligned.m16n8k16.row.col.f32.f16.f16.f32 "
        "{%0,%1,%2,%3},{%4,%5,%6,%7},{%8,%9},{%0,%1,%2,%3};"
        : "+f"(c[0]), "+f"(c[1]), "+f"(c[2]), "+f"(c[3])
        : "r"(a[0]), "r"(a[1]), "r"(a[2]), "r"(a[3]), "r"(b[0]), "r"(b[1]));
}
__device__ __forceinline__ unsigned pack_h2(float lo, float hi) {
    __half2 h = __floats2half2_rn(lo, hi);
    return *reinterpret_cast<unsigned*>(&h);
}
__device__ __forceinline__ unsigned h2bits(__half2 h) {
    return *reinterpret_cast<unsigned*>(&h);
}

// ---------------- core fp16 GEMM tile (B source fp32): 128M x 128N, K=256 ----
// 8 warps (4m x 2n), warp tile 32x64, BK=16, double-buffered.
// ALL structure compile-time: BSTR = B row stride, MODE (1: window-major half
// store; 2: vs scatter store x0.5), DIFF (B = xb - xb2). Keeps regs <= 128.
#define SA2 136

template<int BSTR, int MODE, bool DIFF>
__device__ __forceinline__ void gemm_f16_core(
    const float* __restrict__ wb,
    const float* __restrict__ xb,
    const float* __restrict__ xb2,
    int n0,
    __half* __restrict__ obh,
    float* __restrict__ obf,
    int hofs)
{
    __shared__ __align__(16) unsigned As[2][8*SA2];
    __shared__ __align__(16) unsigned Bs[2][8*SA2];

    int tid  = threadIdx.x;
    int lane = tid & 31, warp = tid >> 5;
    int wm = warp >> 1, wn = warp & 1;
    int gid = lane >> 2, tig = lane & 3;

    float acc[2][8][4];
    #pragma unroll
    for (int mt = 0; mt < 2; mt++)
        #pragma unroll
        for (int nt = 0; nt < 8; nt++)
            #pragma unroll
            for (int i = 0; i < 4; i++) acc[mt][nt][i] = 0.f;

    int arow = tid & 127, akp = (tid >> 7) * 4;
    int bkp  = tid >> 5,  bn4 = (tid & 31) * 4;

    {
        float4 a0 = *(const float4*)(wb + (size_t)arow*CC + akp*2);
        float4 a1 = *(const float4*)(wb + (size_t)arow*CC + akp*2 + 4);
        float4 b0 = *(const float4*)(xb + (size_t)(2*bkp  )*BSTR + n0 + bn4);
        float4 b1 = *(const float4*)(xb + (size_t)(2*bkp+1)*BSTR + n0 + bn4);
        if (DIFF) {
            float4 c0 = *(const float4*)(xb2 + (size_t)(2*bkp  )*BSTR + n0 + bn4);
            float4 c1 = *(const float4*)(xb2 + (size_t)(2*bkp+1)*BSTR + n0 + bn4);
            b0.x -= c0.x; b0.y -= c0.y; b0.z -= c0.z; b0.w -= c0.w;
            b1.x -= c1.x; b1.y -= c1.y; b1.z -= c1.z; b1.w -= c1.w;
        }
        As[0][(akp+0)*SA2 + arow] = pack_h2(a0.x, a0.y);
        As[0][(akp+1)*SA2 + arow] = pack_h2(a0.z, a0.w);
        As[0][(akp+2)*SA2 + arow] = pack_h2(a1.x, a1.y);
        As[0][(akp+3)*SA2 + arow] = pack_h2(a1.z, a1.w);
        *(uint4*)&Bs[0][bkp*SA2 + bn4] =
            make_uint4(pack_h2(b0.x, b1.x), pack_h2(b0.y, b1.y),
                       pack_h2(b0.z, b1.z), pack_h2(b0.w, b1.w));
    }
    __syncthreads();

    #pragma unroll 2
    for (int it = 0; it < 16; it++) {
        int p = it & 1;
        float4 a0, a1, b0, b1;
        if (it < 15) {
            int k0 = (it + 1) * 16;
            a0 = *(const float4*)(wb + (size_t)arow*CC + k0 + akp*2);
            a1 = *(const float4*)(wb + (size_t)arow*CC + k0 + akp*2 + 4);
            b0 = *(const float4*)(xb + (size_t)(k0 + 2*bkp  )*BSTR + n0 + bn4);
            b1 = *(const float4*)(xb + (size_t)(k0 + 2*bkp+1)*BSTR + n0 + bn4);
            if (DIFF) {
                float4 c0 = *(const float4*)(xb2 + (size_t)(k0 + 2*bkp  )*BSTR + n0 + bn4);
                float4 c1 = *(const float4*)(xb2 + (size_t)(k0 + 2*bkp+1)*BSTR + n0 + bn4);
                b0.x -= c0.x; b0.y -= c0.y; b0.z -= c0.z; b0.w -= c0.w;
                b1.x -= c1.x; b1.y -= c1.y; b1.z -= c1.z; b1.w -= c1.w;
            }
        }

        unsigned af[2][4], bf[8][2];
        #pragma unroll
        for (int mt = 0; mt < 2; mt++) {
            int m = wm*32 + mt*16 + gid;
            af[mt][0] = As[p][(tig  )*SA2 + m];
            af[mt][1] = As[p][(tig  )*SA2 + m + 8];
            af[mt][2] = As[p][(tig+4)*SA2 + m];
            af[mt][3] = As[p][(tig+4)*SA2 + m + 8];
        }
        #pragma unroll
        for (int nt = 0; nt < 8; nt++) {
            int n = wn*64 + nt*8 + gid;
            bf[nt][0] = Bs[p][(tig  )*SA2 + n];
            bf[nt][1] = Bs[p][(tig+4)*SA2 + n];
        }
        #pragma unroll
        for (int mt = 0; mt < 2; mt++)
            #pragma unroll
            for (int nt = 0; nt < 8; nt++)
                mma16(acc[mt][nt], af[mt], bf[nt]);

        if (it < 15) {
            int q = p ^ 1;
            As[q][(akp+0)*SA2 + arow] = pack_h2(a0.x, a0.y);
            As[q][(akp+1)*SA2 + arow] = pack_h2(a0.z, a0.w);
            As[q][(akp+2)*SA2 + arow] = pack_h2(a1.x, a1.y);
            As[q][(akp+3)*SA2 + arow] = pack_h2(a1.z, a1.w);
            *(uint4*)&Bs[q][bkp*SA2 + bn4] =
                make_uint4(pack_h2(b0.x, b1.x), pack_h2(b0.y, b1.y),
                           pack_h2(b0.z, b1.z), pack_h2(b0.w, b1.w));
        }
        __syncthreads();
    }

    if (MODE == 1) {
        // window-major fp16 store: one image row y per block
        int y = n0 >> 8, xb0 = n0 & 255;
        int wy = y >> 3, ty = y & 7;
        #pragma unroll
        for (int mt = 0; mt < 2; mt++) {
            int hloc = wm*2 + mt;
            #pragma unroll
            for (int nt = 0; nt < 8; nt++) {
                int x = xb0 + wn*64 + nt*8 + 2*tig;
                size_t a0 = ((size_t)hloc*1024 + wy*32 + (x>>3))*16;
                int tx = ty*8 + (x&7);
                *reinterpret_cast<__half2*>(obh + (a0 + gid    )*64 + tx) =
                    __floats2half2_rn(acc[mt][nt][0], acc[mt][nt][1]);
                *reinterpret_cast<__half2*>(obh + (a0 + gid + 8)*64 + tx) =
                    __floats2half2_rn(acc[mt][nt][2], acc[mt][nt][3]);
            }
        }
    } else {
        // vs scatter store: rows -> (h, d), cols -> windows; x0.5
        #pragma unroll
        for (int mt = 0; mt < 2; mt++) {
            int r0 = wm*32 + mt*16 + gid;
            int hh = hofs + (r0 >> 4);
            int d0 = r0 & 15, d1 = d0 + 8;
            #pragma unroll
            for (int nt = 0; nt < 8; nt++) {
                int w = n0 + wn*64 + nt*8 + 2*tig;
                obf[((size_t)hh*1024 + w    )*16 + d0] = 0.5f*acc[mt][nt][0];
                obf[((size_t)hh*1024 + w + 1)*16 + d0] = 0.5f*acc[mt][nt][1];
                obf[((size_t)hh*1024 + w    )*16 + d1] = 0.5f*acc[mt][nt][2];
                obf[((size_t)hh*1024 + w + 1)*16 + d1] = 0.5f*acc[mt][nt][3];
            }
        }
    }
}

// ---------------- qkv GEMMs: split so q/k instantiation avoids DIFF path -----
// qkv_qk: by 0,1 -> q (x1); by 2,3 -> k (x2)
__global__ void __launch_bounds__(256, 2) qkv_qk(const float* __restrict__ x1,
                                                 const float* __restrict__ x2,
                                                 const float* __restrict__ Wq)
{
    int b  = blockIdx.z;
    int by = blockIdx.y;
    int n0 = blockIdx.x * 128;
    const float* wb;
    const float* xa;
    __half* ob;
    if (by < 2) {
        wb = Wq + (size_t)(by*128)*CC;
        ob = g_q + ((size_t)(b*16 + by*8) << 20);
        xa = x1;
    } else {
        wb = Wq + (size_t)(256 + (by-2)*128)*CC;
        ob = g_k + ((size_t)(b*16 + (by-2)*8) << 20);
        xa = x2;
    }
    xa += (size_t)b*CC*HW;
    gemm_f16_core<HW, 1, false>(wb, xa, nullptr, n0, ob, nullptr, 0);
}

// qkv_vd: vd = Wv (x1 - x2)
__global__ void __launch_bounds__(256, 2) qkv_vd(const float* __restrict__ x1,
                                                 const float* __restrict__ x2,
                                                 const float* __restrict__ Wq)
{
    int b  = blockIdx.z;
    int by = blockIdx.y;                      // 0..1
    int n0 = blockIdx.x * 128;
    const float* wb = Wq + (size_t)(512 + by*128)*CC;
    __half* ob = g_vd + ((size_t)(b*16 + by*8) << 20);
    const float* xa = x1 + (size_t)b*CC*HW;
    const float* xd = x2 + (size_t)b*CC*HW;
    gemm_f16_core<HW, 1, true>(wb, xa, xd, n0, ob, nullptr, 0);
}

// ---------------- vs GEMM: g_vs = 0.5 * Wv @ g_sx (tensor cores) -------------
__global__ void __launch_bounds__(256, 2) vsg_gemm(const float* __restrict__ Wq)
{
    int b  = blockIdx.z;
    int by = blockIdx.y;                      // 0..1 (weight row tiles)
    int n0 = blockIdx.x * 128;                // windows
    const float* wb = Wq + (size_t)(512 + by*128)*CC;
    const float* xb = g_sx + (size_t)b*CC*1024;
    float* obf = g_vs + (size_t)b*NHH*1024*16;
    gemm_f16_core<1024, 2, false>(wb, xb, nullptr, n0, nullptr, obf, by*8);
}

// ---------------- core fp16 GEMM tile (B source fp16): image store + bias ----
__device__ __forceinline__ void gemm_f16_srch(
    const float* __restrict__ wb,
    const __half* __restrict__ xb,
    float* __restrict__ ob,
    int n0,
    const float* __restrict__ bias)
{
    __shared__ __align__(16) unsigned As[2][8*SA2];
    __shared__ __align__(16) unsigned Bs[2][8*SA2];

    int tid  = threadIdx.x;
    int lane = tid & 31, warp = tid >> 5;
    int wm = warp >> 1, wn = warp & 1;
    int gid = lane >> 2, tig = lane & 3;

    float acc[2][8][4];
    #pragma unroll
    for (int mt = 0; mt < 2; mt++)
        #pragma unroll
        for (int nt = 0; nt < 8; nt++)
            #pragma unroll
            for (int i = 0; i < 4; i++) acc[mt][nt][i] = 0.f;

    int arow = tid & 127, akp = (tid >> 7) * 4;
    int bkp  = tid >> 5,  bn4 = (tid & 31) * 4;

    {
        float4 a0 = *(const float4*)(wb + (size_t)arow*CC + akp*2);
        float4 a1 = *(const float4*)(wb + (size_t)arow*CC + akp*2 + 4);
        uint2 r0 = *(const uint2*)(xb + (size_t)(2*bkp  )*HW + n0 + bn4);
        uint2 r1 = *(const uint2*)(xb + (size_t)(2*bkp+1)*HW + n0 + bn4);
        As[0][(akp+0)*SA2 + arow] = pack_h2(a0.x, a0.y);
        As[0][(akp+1)*SA2 + arow] = pack_h2(a0.z, a0.w);
        As[0][(akp+2)*SA2 + arow] = pack_h2(a1.x, a1.y);
        As[0][(akp+3)*SA2 + arow] = pack_h2(a1.z, a1.w);
        __half2 p0 = *reinterpret_cast<__half2*>(&r0.x);
        __half2 p1 = *reinterpret_cast<__half2*>(&r1.x);
        __half2 q0 = *reinterpret_cast<__half2*>(&r0.y);
        __half2 q1 = *reinterpret_cast<__half2*>(&r1.y);
        *(uint4*)&Bs[0][bkp*SA2 + bn4] =
            make_uint4(h2bits(__lows2half2(p0, p1)), h2bits(__highs2half2(p0, p1)),
                       h2bits(__lows2half2(q0, q1)), h2bits(__highs2half2(q0, q1)));
    }
    __syncthreads();

    #pragma unroll 2
    for (int it = 0; it < 16; it++) {
        int p = it & 1;
        float4 a0, a1;
        uint2 r0, r1;
        if (it < 15) {
            int k0 = (it + 1) * 16;
            a0 = *(const float4*)(wb + (size_t)arow*CC + k0 + akp*2);
            a1 = *(const float4*)(wb + (size_t)arow*CC + k0 + akp*2 + 4);
            r0 = *(const uint2*)(xb + (size_t)(k0 + 2*bkp  )*HW + n0 + bn4);
            r1 = *(const uint2*)(xb + (size_t)(k0 + 2*bkp+1)*HW + n0 + bn4);
        }

        unsigned af[2][4], bf[8][2];
        #pragma unroll
        for (int mt = 0; mt < 2; mt++) {
            int m = wm*32 + mt*16 + gid;
            af[mt][0] = As[p][(tig  )*SA2 + m];
            af[mt][1] = As[p][(tig  )*SA2 + m + 8];
            af[mt][2] = As[p][(tig+4)*SA2 + m];
            af[mt][3] = As[p][(tig+4)*SA2 + m + 8];
        }
        #pragma unroll
        for (int nt = 0; nt < 8; nt++) {
            int n = wn*64 + nt*8 + gid;
            bf[nt][0] = Bs[p][(tig  )*SA2 + n];
            bf[nt][1] = Bs[p][(tig+4)*SA2 + n];
        }
        #pragma unroll
        for (int mt = 0; mt < 2; mt++)
            #pragma unroll
            for (int nt = 0; nt < 8; nt++)
                mma16(acc[mt][nt], af[mt], bf[nt]);

        if (it < 15) {
            int q = p ^ 1;
            As[q][(akp+0)*SA2 + arow] = pack_h2(a0.x, a0.y);
            As[q][(akp+1)*SA2 + arow] = pack_h2(a0.z, a0.w);
            As[q][(akp+2)*SA2 + arow] = pack_h2(a1.x, a1.y);
            As[q][(akp+3)*SA2 + arow] = pack_h2(a1.z, a1.w);
            __half2 p0 = *reinterpret_cast<__half2*>(&r0.x);
            __half2 p1 = *reinterpret_cast<__half2*>(&r1.x);
            __half2 q0 = *reinterpret_cast<__half2*>(&r0.y);
            __half2 q1 = *reinterpret_cast<__half2*>(&r1.y);
            *(uint4*)&Bs[q][bkp*SA2 + bn4] =
                make_uint4(h2bits(__lows2half2(p0, p1)), h2bits(__highs2half2(p0, p1)),
                           h2bits(__lows2half2(q0, q1)), h2bits(__highs2half2(q0, q1)));
        }
        __syncthreads();
    }

    #pragma unroll
    for (int mt = 0; mt < 2; mt++) {
        int r0 = wm*32 + mt*16 + gid;
        float bia0 = bias[r0], bia1 = bias[r0 + 8];
        #pragma unroll
        for (int nt = 0; nt < 8; nt++) {
            int c = n0 + wn*64 + nt*8 + 2*tig;
            *(float2*)(ob + (size_t)r0*HW + c) =
                make_float2(acc[mt][nt][0] + bia0, acc[mt][nt][1] + bia0);
            *(float2*)(ob + (size_t)(r0+8)*HW + c) =
                make_float2(acc[mt][nt][2] + bia1, acc[mt][nt][3] + bia1);
        }
    }
}

// ---------------- pointwise GEMM (BN folded, fp16 src, image layout) ---------
__global__ void __launch_bounds__(256, 2) pw_gemm(float* __restrict__ out)
{
    int b  = blockIdx.z;
    int by = blockIdx.y;
    int n0 = blockIdx.x * 128;
    const float* wb = g_pwf + (size_t)(by*128)*CC;
    const __half* xb = g_u + (size_t)b*CC*HW;
    float* ob = out + (size_t)b*CC*HW + (size_t)(by*128)*HW;
    gemm_f16_srch(wb, xb, ob, n0, g_pwb + by*128);
}

// ---------------- window attention: tensor-core (mma tf32, fp16 inputs) ------
// o = softmax(q k^T*0.25 + bias) @ (0.5*vd) + 0.5*sum_k v2
#define TS 72

__global__ void __launch_bounds__(128, 5) attn_kernel()
{
    int wid = blockIdx.x;                 // 0..2047
    int h   = blockIdx.y;                 // 0..15
    int b   = wid >> 10;
    int w   = wid & 1023;
    int tid = threadIdx.x;
    int lane = tid & 31;
    int mt   = tid >> 5;                  // m-tile 0..3 (16 queries each)
    int g = lane >> 2, t = lane & 3;

    __shared__ unsigned sq [16*TS];       // tf32(q * 0.25*log2e)
    __shared__ unsigned sk [16*TS];       // tf32(k)
    __shared__ unsigned svd[16*TS];       // tf32(0.5*vd)
    __shared__ float svs[16];             // 0.5*sum_k v2

    size_t wbase = ((size_t)((b*NHH + h)*1024 + w)) * 1024;

    if (tid < 16) svs[tid] = g_vs[((size_t)((b*NHH + h)*1024 + w))*16 + tid];

    // coalesced load: thread covers 8 consecutive tokens of one d (fp16 in)
    {
        int j = tid & 7, dd = tid >> 3;
        int t0 = j*8;
        size_t off = wbase + dd*64 + t0;
        uint4 qr = *(const uint4*)(g_q + off);
        uint4 kr = *(const uint4*)(g_k + off);
        uint4 vr = *(const uint4*)(g_vd + off);
        const __half2* qh = reinterpret_cast<const __half2*>(&qr);
        const __half2* kh = reinterpret_cast<const __half2*>(&kr);
        const __half2* vh = reinterpret_cast<const __half2*>(&vr);
        unsigned* spq = &sq[dd*TS + t0];
        unsigned* spk = &sk[dd*TS + t0];
        unsigned* spv = &svd[dd*TS + t0];
        #pragma unroll
        for (int i = 0; i < 4; i++) {
            float2 qf = __half22float2(qh[i]);
            float2 kf = __half22float2(kh[i]);
            float2 vf = __half22float2(vh[i]);
            spq[2*i  ] = f2tf(qf.x * QSCALE);
            spq[2*i+1] = f2tf(qf.y * QSCALE);
            spk[2*i  ] = f2tf(kf.x);
            spk[2*i+1] = f2tf(kf.y);
            spv[2*i  ] = f2tf(0.5f * vf.x);
            spv[2*i+1] = f2tf(0.5f * vf.y);
        }
    }
    __syncthreads();

    int r0q = mt*16 + g;
    unsigned aq[2][4];
    #pragma unroll
    for (int kc = 0; kc < 2; kc++) {
        aq[kc][0] = sq[(kc*8+t  )*TS + r0q];
        aq[kc][1] = sq[(kc*8+t  )*TS + r0q + 8];
        aq[kc][2] = sq[(kc*8+t+4)*TS + r0q];
        aq[kc][3] = sq[(kc*8+t+4)*TS + r0q + 8];
    }

    float acc[8][4];
    #pragma unroll
    for (int ni = 0; ni < 8; ni++) {
        float4 bv = *(const float4*)&g_biasf[(((h*4 + mt)*8 + ni)*128 + lane*4)];
        acc[ni][0] = bv.x; acc[ni][1] = bv.y;
        acc[ni][2] = bv.z; acc[ni][3] = bv.w;
    }

    #pragma unroll
    for (int ni = 0; ni < 8; ni++) {
        unsigned bk[2][2];
        #pragma unroll
        for (int kc = 0; kc < 2; kc++) {
            bk[kc][0] = sk[(kc*8+t  )*TS + ni*8 + g];
            bk[kc][1] = sk[(kc*8+t+4)*TS + ni*8 + g];
        }
        mma8(acc[ni], aq[0], bk[0]);
        mma8(acc[ni], aq[1], bk[1]);
    }

    {
        float m0 = -1e30f, m1 = -1e30f;
        #pragma unroll
        for (int ni = 0; ni < 8; ni++) {
            m0 = fmaxf(m0, fmaxf(acc[ni][0], acc[ni][1]));
            m1 = fmaxf(m1, fmaxf(acc[ni][2], acc[ni][3]));
        }
        m0 = fmaxf(m0, __shfl_xor_sync(0xffffffffu, m0, 1));
        m0 = fmaxf(m0, __shfl_xor_sync(0xffffffffu, m0, 2));
        m1 = fmaxf(m1, __shfl_xor_sync(0xffffffffu, m1, 1));
        m1 = fmaxf(m1, __shfl_xor_sync(0xffffffffu, m1, 2));
        float s0 = 0.f, s1 = 0.f;
        #pragma unroll
        for (int ni = 0; ni < 8; ni++) {
            float p0 = ex2(acc[ni][0] - m0);
            float p1 = ex2(acc[ni][1] - m0);
            float p2 = ex2(acc[ni][2] - m1);
            float p3 = ex2(acc[ni][3] - m1);
            acc[ni][0] = p0; acc[ni][1] = p1;
            acc[ni][2] = p2; acc[ni][3] = p3;
            s0 += p0 + p1; s1 += p2 + p3;
        }
        s0 += __shfl_xor_sync(0xffffffffu, s0, 1);
        s0 += __shfl_xor_sync(0xffffffffu, s0, 2);
        s1 += __shfl_xor_sync(0xffffffffu, s1, 1);
        s1 += __shfl_xor_sync(0xffffffffu, s1, 2);
        float i0 = 1.0f / s0, i1 = 1.0f / s1;
        #pragma unroll
        for (int ni = 0; ni < 8; ni++) {
            acc[ni][0] = __uint_as_float(f2tf(acc[ni][0]*i0));
            acc[ni][1] = __uint_as_float(f2tf(acc[ni][1]*i0));
            acc[ni][2] = __uint_as_float(f2tf(acc[ni][2]*i1));
            acc[ni][3] = __uint_as_float(f2tf(acc[ni][3]*i1));
        }
    }

    float av[2][4];
    #pragma unroll
    for (int no = 0; no < 2; no++) {
        float c0 = svs[no*8 + 2*t];
        float c1 = svs[no*8 + 2*t + 1];
        av[no][0] = c0; av[no][1] = c1;
        av[no][2] = c0; av[no][3] = c1;
    }

    int src0 = (g << 2) | (t >> 1);
    int src1 = src0 + 2;
    bool odd = (t & 1);
    #pragma unroll
    for (int kc2 = 0; kc2 < 8; kc2++) {
        float r0 = acc[kc2][0], r1 = acc[kc2][1];
        float r2 = acc[kc2][2], r3 = acc[kc2][3];
        float x00 = __shfl_sync(0xffffffffu, r0, src0);
        float x01 = __shfl_sync(0xffffffffu, r1, src0);
        float x02 = __shfl_sync(0xffffffffu, r2, src0);
        float x03 = __shfl_sync(0xffffffffu, r3, src0);
        float x10 = __shfl_sync(0xffffffffu, r0, src1);
        float x11 = __shfl_sync(0xffffffffu, r1, src1);
        float x12 = __shfl_sync(0xffffffffu, r2, src1);
        float x13 = __shfl_sync(0xffffffffu, r3, src1);
        unsigned pa[4];
        pa[0] = __float_as_uint(odd ? x01 : x00);
        pa[1] = __float_as_uint(odd ? x03 : x02);
        pa[2] = __float_as_uint(odd ? x11 : x10);
        pa[3] = __float_as_uint(odd ? x13 : x12);
        unsigned bv[2][2];
        #pragma unroll
        for (int no = 0; no < 2; no++) {
            bv[no][0] = svd[(no*8+g)*TS + kc2*8 + t];
            bv[no][1] = svd[(no*8+g)*TS + kc2*8 + t + 4];
        }
        mma8(av[0], pa, bv[0]);
        mma8(av[1], pa, bv[1]);
    }

    float* op = g_o + wbase;
    int q0 = mt*16 + g;
    #pragma unroll
    for (int no = 0; no < 2; no++) {
        int d0 = no*8 + 2*t;
        op[(d0  )*64 + q0    ] = av[no][0];
        op[(d0+1)*64 + q0    ] = av[no][1];
        op[(d0  )*64 + q0 + 8] = av[no][2];
        op[(d0+1)*64 + q0 + 8] = av[no][3];
    }
}

// ---------------- FUSED pools + pad_out + depthwise (fp16 u out) -------------
__global__ void __launch_bounds__(256) pooldw_kernel(const float* __restrict__ dw)
{
    __shared__ float so[47][48];
    __shared__ float st[39][41];
    __shared__ float sdw[64];
    int bc = blockIdx.z;                       // b*256 + c
    int b = bc >> 8, c = bc & 255;
    int y0 = blockIdx.y*32, x0 = blockIdx.x*32;
    const float* ob = g_o + ((size_t)(b*16 + (c>>4)) << 20) + (size_t)(c & 15)*64;
    int tid = threadIdx.x;
    if (tid < 64) sdw[tid] = dw[c*64 + tid];

    for (int idx = tid; idx < 47*47; idx += 256) {
        int r = idx / 47, cl = idx - r*47;
        int gy = y0 - 6 + r, gx = x0 - 6 + cl;
        float v = 0.f;
        if (gy >= 0 && gy <= 256 && gx >= 0 && gx <= 256) {
            int yy = (gy == 256) ? 254 : gy;
            int xx = (gx == 256) ? 254 : gx;
            v = ob[((size_t)((yy>>3)*32 + (xx>>3)))*1024 + (yy&7)*8 + (xx&7)];
        }
        so[r][cl] = v;
    }
    __syncthreads();

    for (int idx = tid; idx < 39*39; idx += 256) {
        int r = idx / 39, cl = idx - r*39;
        int ty = y0 - 3 + r, tx = x0 - 3 + cl;
        float v = 0.f;
        if (ty >= 0 && ty < 256 && tx >= 0 && tx < 256) {
            float sx = 0.f, sy = 0.f;
            #pragma unroll
            for (int d2 = 0; d2 < 8; d2++) {
                sx += so[r + d2][cl + 3];
                sy += so[r + 3][cl + d2];
            }
            v = (sx + sy)*0.125f;
        }
        st[r][cl] = v;
    }
    __syncthreads();

    int oy = tid >> 3, ox = (tid & 7)*4;
    float a0 = 0.f, a1 = 0.f, a2 = 0.f, a3 = 0.f;
    #pragma unroll
    for (int ky = 0; ky < 8; ky++) {
        const float* row = &st[oy+ky][ox];
        #pragma unroll
        for (int kx = 0; kx < 8; kx++) {
            float wv = sdw[ky*8 + kx];
            a0 += wv*row[kx];
            a1 += wv*row[kx+1];
            a2 += wv*row[kx+2];
            a3 += wv*row[kx+3];
        }
    }
    __half* up = g_u + (size_t)bc*HW + (size_t)(y0+oy)*WIMG + x0 + ox;
    __half2 h0 = __floats2half2_rn(a0, a1);
    __half2 h1 = __floats2half2_rn(a2, a3);
    uint2 pkt = make_uint2(h2bits(h0), h2bits(h1));
    *(uint2*)up = pkt;
}

// ---------------- launch ----------------
extern "C" void kernel_launch(void* const* d_in, const int* in_sizes, int n_in,
                              void* d_out, int out_size)
{
    const float* x1       = (const float*)d_in[0];
    const float* x2       = (const float*)d_in[1];
    const float* qkv_w    = (const float*)d_in[2];
    const float* rel_bias = (const float*)d_in[3];
    const float* dw_w     = (const float*)d_in[4];
    const float* bn_g     = (const float*)d_in[5];
    const float* bn_b     = (const float*)d_in[6];
    const float* bn_m     = (const float*)d_in[7];
    const float* bn_v     = (const float*)d_in[8];
    const float* pw_w     = (const float*)d_in[9];
    float* out = (float*)d_out;

    prep_kernel<<<256, 256>>>(pw_w, bn_g, bn_b, bn_m, bn_v);
    bias_prep<<<dim3(NHH, 4, 8), 32>>>(rel_bias);
    xsum_kernel<<<dim3(32, CC, BB), 256>>>(x2);
    vsg_gemm<<<dim3(8, 2, BB), 256>>>(qkv_w);
    qkv_qk<<<dim3(512, 4, BB), 256>>>(x1, x2, qkv_w);
    qkv_vd<<<dim3(512, 2, BB), 256>>>(x1, x2, qkv_w);
    attn_kernel<<<dim3(2048, NHH), 128>>>();
    pooldw_kernel<<<dim3(8, 8, BB*CC), 256>>>(dw_w);
    pw_gemm<<<dim3(512, 2, BB), 256>>>(out);
}